// round 9
// baseline (speedup 1.0000x reference)
#include <cuda_runtime.h>

// Problem constants (fixed by setup_inputs)
#define NB        64
#define SD        52
#define CELLS     (SD * SD)             // 2704
#define CH        255
#define QCELLS    4
#define NQUADS    (NB * CELLS / QCELLS) // 43264
#define QPI       (CELLS / QCELLS)      // 676
#define NCELLS    (NB * CELLS)          // 173056
#define EPSF      1e-6f
#define IOU_T     0.7f
#define SCALE_IDX 2

// Packed per-cell metadata: idx_t[0..2] (2b each) + have_obj[0..2] (1b each).
__device__ unsigned g_meta[NCELLS];

__global__ void zero_out_kernel(float* out) {
    int t = threadIdx.x;
    if (t < 257) out[t] = 0.0f;
}

__device__ __forceinline__ float warp_sum(float v) {
    #pragma unroll
    for (int o = 16; o > 0; o >>= 1) v += __shfl_down_sync(0xffffffffu, v, o);
    return v;
}

// ---------------------------------------------------------------------------
// Kernel 1: box fields, IOU/argmax, coord/obj/noobj losses, meta write.
// One warp = 4 cells, 8 lanes per cell (structure of the best kernel so far).
// ---------------------------------------------------------------------------
__global__ __launch_bounds__(128, 8) void fields_kernel(
    const float* __restrict__ yhat,
    const float* __restrict__ ytru,
    const float* __restrict__ anchors,
    float* __restrict__ out)
{
    const int wl   = threadIdx.x >> 5;
    const int lane = threadIdx.x & 31;
    const int quad = blockIdx.x * 4 + wl;     // 0..43263
    const int n    = quad / QPI;
    const int c0   = (quad % QPI) * QCELLS;

    const int g   = lane >> 3;
    const int sub = lane & 7;
    const int cellIdx = c0 + g;
    const int gi = cellIdx / SD;
    const int gj = cellIdx % SD;

    const size_t base = ((size_t)n * CELLS + cellIdx) * CH;
    const float* Hb = yhat + base;
    const float* Yb = ytru + base;

    const float invS = 1.0f / (float)SD;
    const float fj = (float)gj, fi = (float)gi;

    float hcx[3], hcy[3], hw[3], hh[3], hcf[3];
    float ycx[3], ycy[3], yw[3], yh[3], ycf[3];
    #pragma unroll
    for (int b = 0; b < 3; b++) {
        const float* hb = Hb + b * 85;
        const float* yb = Yb + b * 85;
        hcx[b] = (__ldg(hb + 0) + fj) * invS;
        hcy[b] = (__ldg(hb + 1) + fi) * invS;
        hw[b]  =  __ldg(hb + 2);
        hh[b]  =  __ldg(hb + 3);
        hcf[b] =  __ldg(hb + 4);
        ycx[b] = (__ldg(yb + 0) + fj) * invS;
        ycy[b] = (__ldg(yb + 1) + fi) * invS;
        yw[b]  =  __ldg(yb + 2);
        yh[b]  =  __ldg(yb + 3);
        ycf[b] =  __ldg(yb + 4);
    }

    // IOU 3x3: per-pb max -> noobj; per-tb argmax -> responsible predictor.
    int   idx_t[3];
    float best_t[3] = {-1.0f, -1.0f, -1.0f};
    float noobj_acc = 0.0f;
    #pragma unroll
    for (int pb = 0; pb < 3; pb++) {
        float px1 = hcx[pb] - 0.5f * hw[pb], px2 = hcx[pb] + 0.5f * hw[pb];
        float py1 = hcy[pb] - 0.5f * hh[pb], py2 = hcy[pb] + 0.5f * hh[pb];
        float pa  = hw[pb] * hh[pb];
        float m = -1.0f;
        #pragma unroll
        for (int tb = 0; tb < 3; tb++) {
            float wi = fmaxf(fminf(px2, ycx[tb] + 0.5f * yw[tb]) -
                             fmaxf(px1, ycx[tb] - 0.5f * yw[tb]), 0.0f);
            float hi = fmaxf(fminf(py2, ycy[tb] + 0.5f * yh[tb]) -
                             fmaxf(py1, ycy[tb] - 0.5f * yh[tb]), 0.0f);
            float inter = wi * hi;
            float uni = pa + yw[tb] * yh[tb] - inter;
            float iou = inter / (uni + EPSF);
            m = fmaxf(m, iou);
            if (iou > best_t[tb]) { best_t[tb] = iou; idx_t[tb] = pb; }
        }
        if (sub == 0 && m < IOU_T) noobj_acc += hcf[pb] * hcf[pb];  // NO_OBJ_V3
    }

    float coord_acc = 0.0f, obj_acc = 0.0f;
    if (sub == 0) {
        const float* anc = anchors + SCALE_IDX * 6;
        #pragma unroll
        for (int tb = 0; tb < 3; tb++) {
            int pb = idx_t[tb];
            float ho = (ycf[tb] > 0.0f) ? 1.0f : 0.0f;
            float aw_p = __ldg(anc + pb * 2), ah_p = __ldg(anc + pb * 2 + 1);
            float aw_t = __ldg(anc + tb * 2), ah_t = __ldg(anc + tb * 2 + 1);
            float dx = (hcx[pb] - ycx[tb]) * (float)SD;
            float dy = (hcy[pb] - ycy[tb]) * (float)SD;
            float dlw = __logf(hw[pb] / aw_p + EPSF) - __logf(yw[tb] / aw_t + EPSF);
            float dlh = __logf(hh[pb] / ah_p + EPSF) - __logf(yh[tb] / ah_t + EPSF);
            float c = dx * dx + dy * dy + dlw * dlw + dlh * dlh;
            coord_acc += c * ho * (2.0f - yw[tb] * yh[tb]);   // SCALE_COORD
            float dc = hcf[pb] - ycf[tb];
            obj_acc += dc * dc * ho;

            // Pack meta + store (one lane per cell; 4 consecutive words/warp).
        }
        unsigned meta = (unsigned)idx_t[0] | ((unsigned)idx_t[1] << 2) |
                        ((unsigned)idx_t[2] << 4) |
                        ((ycf[0] > 0.0f ? 1u : 0u) << 6) |
                        ((ycf[1] > 0.0f ? 1u : 0u) << 7) |
                        ((ycf[2] > 0.0f ? 1u : 0u) << 8);
        g_meta[n * CELLS + cellIdx] = meta;
    }

    coord_acc = warp_sum(coord_acc);
    noobj_acc = warp_sum(noobj_acc);
    obj_acc   = warp_sum(obj_acc);

    if (lane == 0) {
        // layout: coord[0:64) class[64:128) noobj[128:192) obj[192:256) prior
        atomicAdd(out + 0 * NB + n, coord_acc);
        atomicAdd(out + 2 * NB + n, noobj_acc);
        atomicAdd(out + 3 * NB + n, obj_acc);
    }
}

// ---------------------------------------------------------------------------
// Kernel 2: class loss. One warp = 16 cells (16 | 2704 -> no image straddle).
// One coalesced meta load, then 288 independent coalesced class LDGs.
// No branches around loads (ho as multiplier) so loads batch freely.
// ---------------------------------------------------------------------------
__global__ __launch_bounds__(256) void class_kernel(
    const float* __restrict__ yhat,
    const float* __restrict__ ytru,
    float* __restrict__ out)
{
    const int gw   = blockIdx.x * 8 + (threadIdx.x >> 5);  // 0..10815
    const int lane = threadIdx.x & 31;
    const int c0   = gw * 16;             // first cell of this warp's chunk
    const int n    = c0 / CELLS;          // image (constant over chunk)

    unsigned mv = 0;
    if (lane < 16) mv = g_meta[c0 + lane];

    const float* Hb = yhat + (size_t)c0 * CH;
    const float* Yb = ytru + (size_t)c0 * CH;

    float acc = 0.0f;
    #pragma unroll 4
    for (int i = 0; i < 16; i++) {
        unsigned m = __shfl_sync(0xffffffffu, mv, i);
        const float* Hc = Hb + i * CH;
        const float* Yc = Yb + i * CH;
        #pragma unroll
        for (int tb = 0; tb < 3; tb++) {
            int   pb = (m >> (2 * tb)) & 3;
            float ho = (float)((m >> (6 + tb)) & 1u);
            const float* h = Hc + pb * 85 + 5;
            const float* y = Yc + tb * 85 + 5;
            float d0 = __ldg(h + lane)      - __ldg(y + lane);
            float d1 = __ldg(h + lane + 32) - __ldg(y + lane + 32);
            float s = d0 * d0 + d1 * d1;
            if (lane < 16) {
                float d2 = __ldg(h + lane + 64) - __ldg(y + lane + 64);
                s += d2 * d2;
            }
            acc += s * ho;
        }
    }

    acc = warp_sum(acc);
    if (lane == 0)
        atomicAdd(out + 1 * NB + n, acc);   // class slot [64:128)
}

extern "C" void kernel_launch(void* const* d_in, const int* in_sizes, int n_in,
                              void* d_out, int out_size) {
    const float* yhat    = (const float*)d_in[0];
    const float* y       = (const float*)d_in[1];
    const float* anchors = (const float*)d_in[2];
    float* out = (float*)d_out;

    zero_out_kernel<<<1, 288>>>(out);
    fields_kernel<<<NQUADS / 4, 128>>>(yhat, y, anchors, out);   // 10816 blocks
    class_kernel<<<NCELLS / 16 / 8, 256>>>(yhat, y, out);        // 1352 blocks
}